// round 3
// baseline (speedup 1.0000x reference)
#include <cuda_runtime.h>

// ---------------------------------------------------------------------------
// GINConv: out = relu((x + segment_sum(x[src], dst)) @ W1 + b1) @ W2 + b2
// N=50000 nodes, E=640000 edges, D=128. fp32 throughout.
// edge_index arrives as int32 (JAX x64 disabled downcasts int64 -> int32).
//
//   K1: g_agg = x                       (vectorized copy)
//   K2: warp-per-edge scatter-add, scalar REDG.ADD.F32, column-interleaved
//       so every LDG / REDG instruction is a fully coalesced 128B access.
//   K3: fused MLP: one 128-row tile per block; W1, W2, biases and the
//       transposed input tile in ~195 KB dynamic smem; 256-thread / 8x8
//       register-tile SGEMM, GEMM1 -> relu -> transposed writeback -> GEMM2.
// ---------------------------------------------------------------------------

#define DIM      128
#define MAX_N    50000
#define TILE_M   128
#define SX       132   // padded k-major stride for X/H tile

__device__ float g_agg[MAX_N * DIM];  // scratch accumulator (25.6 MB)

// ---------------------------------------------------------------------------
// K1: agg = x
// ---------------------------------------------------------------------------
__global__ void init_agg_kernel(const float4* __restrict__ x4, int n4) {
    int i = blockIdx.x * blockDim.x + threadIdx.x;
    if (i < n4) {
        reinterpret_cast<float4*>(g_agg)[i] = x4[i];
    }
}

// ---------------------------------------------------------------------------
// K2: scatter-add. One warp per edge; lane l owns columns l, l+32, l+64, l+96.
// Each of the 4 LDG.32 and 4 REDG.ADD.F32 per warp is a contiguous 128B access.
// ---------------------------------------------------------------------------
__global__ void scatter_kernel(const float* __restrict__ x,
                               const int* __restrict__ ei,
                               int E) {
    int t    = blockIdx.x * blockDim.x + threadIdx.x;
    int e    = t >> 5;
    int lane = t & 31;
    if (e >= E) return;

    int src = ei[e];        // all lanes same addr -> broadcast
    int dst = ei[E + e];

    const float* srow = x     + (size_t)src * DIM;
    float*       drow = g_agg + (size_t)dst * DIM;

    float v0 = srow[lane];
    float v1 = srow[lane + 32];
    float v2 = srow[lane + 64];
    float v3 = srow[lane + 96];
    atomicAdd(&drow[lane],      v0);
    atomicAdd(&drow[lane + 32], v1);
    atomicAdd(&drow[lane + 64], v2);
    atomicAdd(&drow[lane + 96], v3);
}

// ---------------------------------------------------------------------------
// K3: fused MLP. grid = ceil(M/128) blocks, 256 threads.
// ---------------------------------------------------------------------------
__global__ void __launch_bounds__(256, 1)
mlp_kernel(const float* __restrict__ W1,
           const float* __restrict__ b1,
           const float* __restrict__ W2,
           const float* __restrict__ b2,
           float* __restrict__ out,
           int M) {
    extern __shared__ float smem[];
    float* Xs  = smem;                   // SX * DIM floats
    float* W1s = Xs  + SX * DIM;
    float* W2s = W1s + DIM * DIM;
    float* b1s = W2s + DIM * DIM;
    float* b2s = b1s + DIM;

    const int tid = threadIdx.x;
    const int tx  = tid & 15;
    const int ty  = tid >> 4;
    const int m0  = ty * 8;
    const int n0  = tx * 8;
    const int rowBase = blockIdx.x * TILE_M;

    // --- load W1, W2 (coalesced) ---
    {
        const float4* w1v = reinterpret_cast<const float4*>(W1);
        const float4* w2v = reinterpret_cast<const float4*>(W2);
        float4* W1sv = reinterpret_cast<float4*>(W1s);
        float4* W2sv = reinterpret_cast<float4*>(W2s);
        #pragma unroll
        for (int i = tid; i < DIM * DIM / 4; i += 256) {
            W1sv[i] = w1v[i];
            W2sv[i] = w2v[i];
        }
        if (tid < DIM) {
            b1s[tid] = b1[tid];
            b2s[tid] = b2[tid];
        }
    }

    // --- load input tile transposed into Xs[k][m] (zero-pad past M) ---
    {
        const float4* in4 = reinterpret_cast<const float4*>(g_agg);
        #pragma unroll
        for (int i = tid; i < TILE_M * (DIM / 4); i += 256) {
            int m  = i >> 5;
            int k4 = i & 31;
            int gm = rowBase + m;
            float4 v = make_float4(0.f, 0.f, 0.f, 0.f);
            if (gm < M) v = in4[gm * (DIM / 4) + k4];
            Xs[(k4 * 4 + 0) * SX + m] = v.x;
            Xs[(k4 * 4 + 1) * SX + m] = v.y;
            Xs[(k4 * 4 + 2) * SX + m] = v.z;
            Xs[(k4 * 4 + 3) * SX + m] = v.w;
        }
    }
    __syncthreads();

    // --- GEMM1: acc = Xtile @ W1 ---
    float acc[8][8];
    #pragma unroll
    for (int i = 0; i < 8; i++)
        #pragma unroll
        for (int j = 0; j < 8; j++) acc[i][j] = 0.f;

    #pragma unroll 4
    for (int k = 0; k < DIM; k++) {
        float4 a0 = *reinterpret_cast<const float4*>(&Xs[k * SX + m0]);
        float4 a1 = *reinterpret_cast<const float4*>(&Xs[k * SX + m0 + 4]);
        float4 w0 = *reinterpret_cast<const float4*>(&W1s[k * DIM + n0]);
        float4 w1 = *reinterpret_cast<const float4*>(&W1s[k * DIM + n0 + 4]);
        float a[8] = {a0.x, a0.y, a0.z, a0.w, a1.x, a1.y, a1.z, a1.w};
        float b[8] = {w0.x, w0.y, w0.z, w0.w, w1.x, w1.y, w1.z, w1.w};
        #pragma unroll
        for (int i = 0; i < 8; i++)
            #pragma unroll
            for (int j = 0; j < 8; j++)
                acc[i][j] += a[i] * b[j];
    }

    __syncthreads();   // all GEMM1 reads of Xs done before overwrite

    // --- relu(+b1), write back transposed into Xs as Hs[k][m] ---
    #pragma unroll
    for (int j = 0; j < 8; j++) {
        float bj = b1s[n0 + j];
        #pragma unroll
        for (int i = 0; i < 8; i++) {
            float h = acc[i][j] + bj;
            h = h > 0.f ? h : 0.f;
            Xs[(n0 + j) * SX + (m0 + i)] = h;
        }
    }
    __syncthreads();

    // --- GEMM2: acc = Htile @ W2 ---
    #pragma unroll
    for (int i = 0; i < 8; i++)
        #pragma unroll
        for (int j = 0; j < 8; j++) acc[i][j] = 0.f;

    #pragma unroll 4
    for (int k = 0; k < DIM; k++) {
        float4 a0 = *reinterpret_cast<const float4*>(&Xs[k * SX + m0]);
        float4 a1 = *reinterpret_cast<const float4*>(&Xs[k * SX + m0 + 4]);
        float4 w0 = *reinterpret_cast<const float4*>(&W2s[k * DIM + n0]);
        float4 w1 = *reinterpret_cast<const float4*>(&W2s[k * DIM + n0 + 4]);
        float a[8] = {a0.x, a0.y, a0.z, a0.w, a1.x, a1.y, a1.z, a1.w};
        float b[8] = {w0.x, w0.y, w0.z, w0.w, w1.x, w1.y, w1.z, w1.w};
        #pragma unroll
        for (int i = 0; i < 8; i++)
            #pragma unroll
            for (int j = 0; j < 8; j++)
                acc[i][j] += a[i] * b[j];
    }

    // --- +b2, store (float4, coalesced), guard tail rows ---
    float4 bb0 = *reinterpret_cast<const float4*>(&b2s[n0]);
    float4 bb1 = *reinterpret_cast<const float4*>(&b2s[n0 + 4]);
    #pragma unroll
    for (int i = 0; i < 8; i++) {
        int gm = rowBase + m0 + i;
        if (gm < M) {
            float4 o0 = make_float4(acc[i][0] + bb0.x, acc[i][1] + bb0.y,
                                    acc[i][2] + bb0.z, acc[i][3] + bb0.w);
            float4 o1 = make_float4(acc[i][4] + bb1.x, acc[i][5] + bb1.y,
                                    acc[i][6] + bb1.z, acc[i][7] + bb1.w);
            *reinterpret_cast<float4*>(&out[gm * DIM + n0])     = o0;
            *reinterpret_cast<float4*>(&out[gm * DIM + n0 + 4]) = o1;
        }
    }
}

// ---------------------------------------------------------------------------
// launch
// ---------------------------------------------------------------------------
extern "C" void kernel_launch(void* const* d_in, const int* in_sizes, int n_in,
                              void* d_out, int out_size) {
    const float* x   = (const float*)d_in[0];
    const int*   ei  = (const int*)d_in[1];    // int32 edge_index [2, E]
    const float* W1  = (const float*)d_in[2];
    const float* b1  = (const float*)d_in[3];
    const float* W2  = (const float*)d_in[4];
    const float* b2  = (const float*)d_in[5];
    float*       out = (float*)d_out;

    const int M = in_sizes[0] / DIM;      // 50000
    const int E = in_sizes[1] / 2;        // 640000

    // K1: agg = x
    int n4 = M * (DIM / 4);
    init_agg_kernel<<<(n4 + 255) / 256, 256>>>(
        reinterpret_cast<const float4*>(x), n4);

    // K2: scatter-add (warp per edge, 8 warps/block)
    int eBlocks = (E + 7) / 8;
    scatter_kernel<<<eBlocks, 256>>>(x, ei, E);

    // K3: fused MLP
    size_t smemBytes = (size_t)(SX * DIM + 2 * DIM * DIM + 2 * DIM) * sizeof(float);
    cudaFuncSetAttribute(mlp_kernel,
                         cudaFuncAttributeMaxDynamicSharedMemorySize,
                         (int)smemBytes);
    int mBlocks = (M + TILE_M - 1) / TILE_M;
    mlp_kernel<<<mBlocks, 256, smemBytes>>>(W1, b1, W2, b2, out, M);
}

// round 5
// speedup vs baseline: 1.4291x; 1.4291x over previous
#include <cuda_runtime.h>
#include <cuda_bf16.h>
#include <cstdint>

// ---------------------------------------------------------------------------
// GINConv: out = relu((x + segment_sum(x[src], dst)) @ W1 + b1) @ W2 + b2
// N=50000, E=640000, D=128, fp32. edge_index int32.
//
//   K0: prep_weights  - W1/W2 -> bf16 hi/lo, transposed [n][k], pitch 136
//   K1: g_agg = x
//   K2: warp-per-edge scatter-add (coalesced REDG.ADD.F32)
//   K3: HMMA MLP      - mma.sync m16n8k16 bf16 (feature-neutral, ptxas-safe),
//                       bf16x3 split: AhBh + AhBl + AlBh, fp32 accum.
// ---------------------------------------------------------------------------

#define DIM    128
#define MAX_N  50000
#define TILE_M 128
#define PA     136                       // padded pitch (elements); 272B rows
#define TBYTES (128 * PA * 2)            // 34816 B per bf16 tile

__device__ float g_agg[MAX_N * DIM];

// W^T hi/lo tiles, [n][k] row-major, pitch PA
__device__ __align__(16) __nv_bfloat16 g_w1h[128 * PA];
__device__ __align__(16) __nv_bfloat16 g_w1l[128 * PA];
__device__ __align__(16) __nv_bfloat16 g_w2h[128 * PA];
__device__ __align__(16) __nv_bfloat16 g_w2l[128 * PA];

__device__ __forceinline__ uint32_t smem_u32(const void* p) {
    uint32_t a;
    asm("{ .reg .u64 t; cvta.to.shared.u64 t, %1; cvt.u32.u64 %0, t; }"
        : "=r"(a) : "l"(p));
    return a;
}

__device__ __forceinline__ void ldmx4(uint32_t addr, uint32_t r[4]) {
    asm volatile("ldmatrix.sync.aligned.m8n8.x4.shared.b16 {%0,%1,%2,%3}, [%4];"
                 : "=r"(r[0]), "=r"(r[1]), "=r"(r[2]), "=r"(r[3]) : "r"(addr));
}

__device__ __forceinline__ void mma16816(float c[4], const uint32_t a[4],
                                         uint32_t b0, uint32_t b1) {
    asm volatile("mma.sync.aligned.m16n8k16.row.col.f32.bf16.bf16.f32 "
                 "{%0,%1,%2,%3}, {%4,%5,%6,%7}, {%8,%9}, {%0,%1,%2,%3};"
                 : "+f"(c[0]), "+f"(c[1]), "+f"(c[2]), "+f"(c[3])
                 : "r"(a[0]), "r"(a[1]), "r"(a[2]), "r"(a[3]), "r"(b0), "r"(b1));
}

__device__ __forceinline__ void bf16_split(float a, __nv_bfloat16& h, __nv_bfloat16& l) {
    h = __float2bfloat16_rn(a);
    l = __float2bfloat16_rn(a - __bfloat162float(h));
}

// ---------------------------------------------------------------------------
// K0: weight split + transpose. W[k][n] -> tiles[n*PA + k]
// ---------------------------------------------------------------------------
__global__ void prep_weights(const float* __restrict__ W1,
                             const float* __restrict__ W2) {
    int idx = blockIdx.x * blockDim.x + threadIdx.x;
    if (idx >= DIM * DIM) return;
    int k = idx >> 7, n = idx & 127;
    int o = n * PA + k;
    __nv_bfloat16 h, l;
    bf16_split(W1[idx], h, l);
    g_w1h[o] = h; g_w1l[o] = l;
    bf16_split(W2[idx], h, l);
    g_w2h[o] = h; g_w2l[o] = l;
}

// ---------------------------------------------------------------------------
// K1: agg = x
// ---------------------------------------------------------------------------
__global__ void init_agg_kernel(const float4* __restrict__ x4, int n4) {
    int i = blockIdx.x * blockDim.x + threadIdx.x;
    if (i < n4) reinterpret_cast<float4*>(g_agg)[i] = x4[i];
}

// ---------------------------------------------------------------------------
// K2: scatter-add, one warp per edge, coalesced LDG/REDG
// ---------------------------------------------------------------------------
__global__ void scatter_kernel(const float* __restrict__ x,
                               const int* __restrict__ ei, int E) {
    int t = blockIdx.x * blockDim.x + threadIdx.x;
    int e = t >> 5, lane = t & 31;
    if (e >= E) return;
    int src = ei[e];
    int dst = ei[E + e];
    const float* srow = x + (size_t)src * DIM;
    float* drow = g_agg + (size_t)dst * DIM;
    float v0 = srow[lane], v1 = srow[lane + 32];
    float v2 = srow[lane + 64], v3 = srow[lane + 96];
    atomicAdd(&drow[lane],      v0);
    atomicAdd(&drow[lane + 32], v1);
    atomicAdd(&drow[lane + 64], v2);
    atomicAdd(&drow[lane + 96], v3);
}

// ---------------------------------------------------------------------------
// K3: HMMA MLP. 256 threads / 8 warps; warp w owns m-rows [16w, 16w+16).
// smem layout (bytes):
//   b1s: 0..512 | b2s: 512..1024 | Ah: 1024 | Al | W1h | W1l | W2h | W2l
// ---------------------------------------------------------------------------
#define SM_AH   1024
#define SM_AL   (SM_AH  + TBYTES)
#define SM_W1H  (SM_AL  + TBYTES)
#define SM_W1L  (SM_W1H + TBYTES)
#define SM_W2H  (SM_W1L + TBYTES)
#define SM_W2L  (SM_W2H + TBYTES)
#define SM_TOT  (SM_W2L + TBYTES)

// one GEMM: acc += Ah*Wh + Ah*Wl + Al*Wh  (all operands smem, bf16)
__device__ __forceinline__ void do_gemm(uint32_t aH, uint32_t aL,
                                        uint32_t wH, uint32_t wL,
                                        float (*acc)[4]) {
    #pragma unroll
    for (int k = 0; k < 8; k++) {
        uint32_t ah[4], al[4];
        ldmx4(aH + k * 32, ah);
        ldmx4(aL + k * 32, al);
        #pragma unroll
        for (int nn = 0; nn < 8; nn++) {
            uint32_t boff = (uint32_t)(nn * 16 * PA * 2 + k * 32);
            uint32_t bh[4], bl[4];
            ldmx4(wH + boff, bh);
            ldmx4(wL + boff, bl);
            mma16816(acc[2*nn],   ah, bh[0], bh[1]);
            mma16816(acc[2*nn],   ah, bl[0], bl[1]);
            mma16816(acc[2*nn],   al, bh[0], bh[1]);
            mma16816(acc[2*nn+1], ah, bh[2], bh[3]);
            mma16816(acc[2*nn+1], ah, bl[2], bl[3]);
            mma16816(acc[2*nn+1], al, bh[2], bh[3]);
        }
    }
}

__global__ void __launch_bounds__(256, 1)
mlp_hmma_kernel(const float* __restrict__ b1,
                const float* __restrict__ b2,
                float* __restrict__ out, int M) {
    extern __shared__ unsigned char sm[];
    const uint32_t sb = smem_u32(sm);
    const int tid  = threadIdx.x;
    const int w    = tid >> 5;
    const int lane = tid & 31;
    const int rowBase = blockIdx.x * TILE_M;

    float* b1s = reinterpret_cast<float*>(sm);
    float* b2s = reinterpret_cast<float*>(sm + 512);
    if (tid < DIM) {
        b1s[tid] = b1[tid];
        b2s[tid] = b2[tid];
    }

    // weight tiles: linear coalesced copy of pre-swizzled scratch
    {
        const uint4* s1h = reinterpret_cast<const uint4*>(g_w1h);
        const uint4* s1l = reinterpret_cast<const uint4*>(g_w1l);
        const uint4* s2h = reinterpret_cast<const uint4*>(g_w2h);
        const uint4* s2l = reinterpret_cast<const uint4*>(g_w2l);
        uint4* d1h = reinterpret_cast<uint4*>(sm + SM_W1H);
        uint4* d1l = reinterpret_cast<uint4*>(sm + SM_W1L);
        uint4* d2h = reinterpret_cast<uint4*>(sm + SM_W2H);
        uint4* d2l = reinterpret_cast<uint4*>(sm + SM_W2L);
        for (int i = tid; i < TBYTES / 16; i += 256) {
            d1h[i] = s1h[i]; d1l[i] = s1l[i];
            d2h[i] = s2h[i]; d2l[i] = s2l[i];
        }
    }

    // A tile: load (x+agg), split bf16 hi/lo into Ah/Al [m][k], pitch PA
    {
        __nv_bfloat16* Ah = reinterpret_cast<__nv_bfloat16*>(sm + SM_AH);
        __nv_bfloat16* Al = reinterpret_cast<__nv_bfloat16*>(sm + SM_AL);
        const float4* in4 = reinterpret_cast<const float4*>(g_agg);
        #pragma unroll
        for (int i = tid; i < TILE_M * 32; i += 256) {
            int m = i >> 5, c = i & 31;
            int gm = rowBase + m;
            float4 v = make_float4(0.f, 0.f, 0.f, 0.f);
            if (gm < M) v = in4[(size_t)gm * 32 + c];
            float vv[4] = {v.x, v.y, v.z, v.w};
            #pragma unroll
            for (int j = 0; j < 4; j++) {
                __nv_bfloat16 h, l;
                bf16_split(vv[j], h, l);
                Ah[m * PA + c * 4 + j] = h;
                Al[m * PA + c * 4 + j] = l;
            }
        }
    }
    __syncthreads();

    // lane-dependent ldmatrix base addresses
    // A: row = m0 + (lane&15), col-half = (lane>>4)*8
    const uint32_t aLaneOff =
        (uint32_t)(((w * 16 + (lane & 15)) * PA + ((lane >> 4) << 3)) * 2);
    // B: row = (lane&7) + ((lane>>4)<<3), col = ((lane>>3)&1)<<3
    const uint32_t bLaneOff =
        (uint32_t)((((lane & 7) + ((lane >> 4) << 3)) * PA
                    + (((lane >> 3) & 1) << 3)) * 2);

    const uint32_t aH = sb + SM_AH + aLaneOff;
    const uint32_t aL = sb + SM_AL + aLaneOff;

    float acc[16][4];
    #pragma unroll
    for (int i = 0; i < 16; i++)
        #pragma unroll
        for (int j = 0; j < 4; j++) acc[i][j] = 0.f;

    // ---- GEMM1 ----
    do_gemm(aH, aL, sb + SM_W1H + bLaneOff, sb + SM_W1L + bLaneOff, acc);

    // ---- epilogue 1: +b1, relu, split, write H into Ah/Al (warp-private rows)
    {
        __nv_bfloat16* Ah = reinterpret_cast<__nv_bfloat16*>(sm + SM_AH);
        __nv_bfloat16* Al = reinterpret_cast<__nv_bfloat16*>(sm + SM_AL);
        int r0 = w * 16 + (lane >> 2);
        int r1 = r0 + 8;
        #pragma unroll
        for (int nc = 0; nc < 16; nc++) {
            int n = nc * 8 + 2 * (lane & 3);
            float f00 = acc[nc][0] + b1s[n];
            float f01 = acc[nc][1] + b1s[n + 1];
            float f10 = acc[nc][2] + b1s[n];
            float f11 = acc[nc][3] + b1s[n + 1];
            f00 = f00 > 0.f ? f00 : 0.f;  f01 = f01 > 0.f ? f01 : 0.f;
            f10 = f10 > 0.f ? f10 : 0.f;  f11 = f11 > 0.f ? f11 : 0.f;
            __nv_bfloat16 h, l;
            bf16_split(f00, h, l); Ah[r0 * PA + n]     = h; Al[r0 * PA + n]     = l;
            bf16_split(f01, h, l); Ah[r0 * PA + n + 1] = h; Al[r0 * PA + n + 1] = l;
            bf16_split(f10, h, l); Ah[r1 * PA + n]     = h; Al[r1 * PA + n]     = l;
            bf16_split(f11, h, l); Ah[r1 * PA + n + 1] = h; Al[r1 * PA + n + 1] = l;
            #pragma unroll
            for (int j = 0; j < 4; j++) acc[nc][j] = 0.f;
        }
    }
    __syncwarp();   // H rows are warp-private; only intra-warp visibility needed

    // ---- GEMM2 ----
    do_gemm(aH, aL, sb + SM_W2H + bLaneOff, sb + SM_W2L + bLaneOff, acc);

    // ---- epilogue 2: +b2, store fp32 ----
    {
        int gm0 = rowBase + w * 16 + (lane >> 2);
        int gm1 = gm0 + 8;
        #pragma unroll
        for (int nc = 0; nc < 16; nc++) {
            int n = nc * 8 + 2 * (lane & 3);
            if (gm0 < M) {
                float2 o = make_float2(acc[nc][0] + b2s[n], acc[nc][1] + b2s[n + 1]);
                *reinterpret_cast<float2*>(&out[(size_t)gm0 * DIM + n]) = o;
            }
            if (gm1 < M) {
                float2 o = make_float2(acc[nc][2] + b2s[n], acc[nc][3] + b2s[n + 1]);
                *reinterpret_cast<float2*>(&out[(size_t)gm1 * DIM + n]) = o;
            }
        }
    }
}

// ---------------------------------------------------------------------------
// launch
// ---------------------------------------------------------------------------
extern "C" void kernel_launch(void* const* d_in, const int* in_sizes, int n_in,
                              void* d_out, int out_size) {
    const float* x   = (const float*)d_in[0];
    const int*   ei  = (const int*)d_in[1];
    const float* W1  = (const float*)d_in[2];
    const float* b1  = (const float*)d_in[3];
    const float* W2  = (const float*)d_in[4];
    const float* b2  = (const float*)d_in[5];
    float*       out = (float*)d_out;

    const int M = in_sizes[0] / DIM;   // 50000
    const int E = in_sizes[1] / 2;     // 640000

    prep_weights<<<(DIM * DIM + 255) / 256, 256>>>(W1, W2);

    int n4 = M * (DIM / 4);
    init_agg_kernel<<<(n4 + 255) / 256, 256>>>(
        reinterpret_cast<const float4*>(x), n4);

    scatter_kernel<<<(E + 7) / 8, 256>>>(x, ei, E);

    cudaFuncSetAttribute(mlp_hmma_kernel,
                         cudaFuncAttributeMaxDynamicSharedMemorySize, SM_TOT);
    int mBlocks = (M + TILE_M - 1) / TILE_M;
    mlp_hmma_kernel<<<mBlocks, 256, SM_TOT>>>(b1, b2, out, M);
}

// round 6
// speedup vs baseline: 1.8789x; 1.3148x over previous
#include <cuda_runtime.h>
#include <cuda_bf16.h>
#include <cstdint>

// ---------------------------------------------------------------------------
// GINConv: out = relu((x + segment_sum(x[src], dst)) @ W1 + b1) @ W2 + b2
// N=50000, E=640000, D=128, fp32, edge_index int32.
//
//   K0: prep_weights + zero deg     K4: scan3 (start/cursor)
//   K1: degree histogram            K5: fill csr_src
//   K2: scan1 (per-1024 chunks)     K6: gather-sum  agg = x + sum x[src]
//   K3: scan2 (chunk partials)      K7: HMMA MLP (bf16x3 split, 4x2 warps)
// ---------------------------------------------------------------------------

#define DIM    128
#define MAX_N  50000
#define MAX_E  640000
#define TILE_M 128
#define PA     136                       // padded pitch (elems), 272B rows
#define TBYTES (128 * PA * 2)            // 34816 B per bf16 tile
#define NCHUNK ((MAX_N + 1023) / 1024)   // 49

__device__ float g_agg[MAX_N * DIM];

__device__ int g_deg[MAX_N];
__device__ int g_incl[MAX_N];
__device__ int g_part[64];
__device__ int g_start[MAX_N];
__device__ int g_cursor[MAX_N];
__device__ int g_csr[MAX_E];

// W^T hi/lo tiles, [n][k] row-major, pitch PA
__device__ __align__(16) __nv_bfloat16 g_w1h[128 * PA];
__device__ __align__(16) __nv_bfloat16 g_w1l[128 * PA];
__device__ __align__(16) __nv_bfloat16 g_w2h[128 * PA];
__device__ __align__(16) __nv_bfloat16 g_w2l[128 * PA];

__device__ __forceinline__ uint32_t smem_u32(const void* p) {
    uint32_t a;
    asm("{ .reg .u64 t; cvta.to.shared.u64 t, %1; cvt.u32.u64 %0, t; }"
        : "=r"(a) : "l"(p));
    return a;
}
__device__ __forceinline__ void ldmx4(uint32_t addr, uint32_t r[4]) {
    asm volatile("ldmatrix.sync.aligned.m8n8.x4.shared.b16 {%0,%1,%2,%3}, [%4];"
                 : "=r"(r[0]), "=r"(r[1]), "=r"(r[2]), "=r"(r[3]) : "r"(addr));
}
__device__ __forceinline__ void mma16816(float c[4], const uint32_t a[4],
                                         uint32_t b0, uint32_t b1) {
    asm volatile("mma.sync.aligned.m16n8k16.row.col.f32.bf16.bf16.f32 "
                 "{%0,%1,%2,%3}, {%4,%5,%6,%7}, {%8,%9}, {%0,%1,%2,%3};"
                 : "+f"(c[0]), "+f"(c[1]), "+f"(c[2]), "+f"(c[3])
                 : "r"(a[0]), "r"(a[1]), "r"(a[2]), "r"(a[3]), "r"(b0), "r"(b1));
}
__device__ __forceinline__ void bf16_split(float a, __nv_bfloat16& h, __nv_bfloat16& l) {
    h = __float2bfloat16_rn(a);
    l = __float2bfloat16_rn(a - __bfloat162float(h));
}

// ---------------------------------------------------------------------------
// K0: weight split/transpose + zero degree counters
// ---------------------------------------------------------------------------
__global__ void prep_zero(const float* __restrict__ W1,
                          const float* __restrict__ W2, int N) {
    int idx = blockIdx.x * blockDim.x + threadIdx.x;
    if (idx < DIM * DIM) {
        int k = idx >> 7, n = idx & 127;
        int o = n * PA + k;
        __nv_bfloat16 h, l;
        bf16_split(W1[idx], h, l);
        g_w1h[o] = h; g_w1l[o] = l;
        bf16_split(W2[idx], h, l);
        g_w2h[o] = h; g_w2l[o] = l;
    }
    if (idx < N) g_deg[idx] = 0;
}

// K1: degree histogram
__global__ void hist_kernel(const int* __restrict__ ei, int E) {
    int e = blockIdx.x * blockDim.x + threadIdx.x;
    if (e < E) atomicAdd(&g_deg[ei[E + e]], 1);
}

// K2: per-chunk inclusive scan (1024 elems/block)
__global__ void scan1_kernel(int N) {
    __shared__ int s[1024];
    int tid = threadIdx.x;
    int idx = blockIdx.x * 1024 + tid;
    int v = (idx < N) ? g_deg[idx] : 0;
    s[tid] = v;
    __syncthreads();
    #pragma unroll
    for (int off = 1; off < 1024; off <<= 1) {
        int t = (tid >= off) ? s[tid - off] : 0;
        __syncthreads();
        s[tid] += t;
        __syncthreads();
    }
    if (idx < N) g_incl[idx] = s[tid];
    if (tid == 1023) g_part[blockIdx.x] = s[1023];
}

// K3: scan chunk partials -> exclusive offsets (single block, 64 threads)
__global__ void scan2_kernel(int nb) {
    __shared__ int s[64];
    int tid = threadIdx.x;
    int v = (tid < nb) ? g_part[tid] : 0;
    int orig = v;
    s[tid] = v;
    __syncthreads();
    #pragma unroll
    for (int off = 1; off < 64; off <<= 1) {
        int t = (tid >= off) ? s[tid - off] : 0;
        __syncthreads();
        s[tid] += t;
        __syncthreads();
    }
    if (tid < nb) g_part[tid] = s[tid] - orig;   // exclusive
}

// K4: finalize row starts + working cursors
__global__ void scan3_kernel(int N) {
    int idx = blockIdx.x * blockDim.x + threadIdx.x;
    if (idx >= N) return;
    int incl = g_incl[idx] + g_part[idx >> 10];
    int start = incl - g_deg[idx];
    g_start[idx] = start;
    g_cursor[idx] = start;
}

// K5: fill CSR source list
__global__ void fill_kernel(const int* __restrict__ ei, int E) {
    int e = blockIdx.x * blockDim.x + threadIdx.x;
    if (e >= E) return;
    int src = ei[e];
    int dst = ei[E + e];
    int pos = atomicAdd(&g_cursor[dst], 1);
    g_csr[pos] = src;
}

// K6: gather-sum. One warp per node: agg[i] = x[i] + sum_j x[csr[j]]
__global__ void gather_kernel(const float4* __restrict__ x4, int N) {
    int node = blockIdx.x * 8 + (threadIdx.x >> 5);
    int lane = threadIdx.x & 31;
    if (node >= N) return;

    float4 acc = x4[(size_t)node * 32 + lane];
    int j   = g_start[node];
    int end = j + g_deg[node];
    for (; j + 1 < end; j += 2) {
        int s0 = g_csr[j];
        int s1 = g_csr[j + 1];
        float4 a = x4[(size_t)s0 * 32 + lane];
        float4 b = x4[(size_t)s1 * 32 + lane];
        acc.x += a.x; acc.y += a.y; acc.z += a.z; acc.w += a.w;
        acc.x += b.x; acc.y += b.y; acc.z += b.z; acc.w += b.w;
    }
    if (j < end) {
        int s0 = g_csr[j];
        float4 a = x4[(size_t)s0 * 32 + lane];
        acc.x += a.x; acc.y += a.y; acc.z += a.z; acc.w += a.w;
    }
    reinterpret_cast<float4*>(g_agg)[(size_t)node * 32 + lane] = acc;
}

// ---------------------------------------------------------------------------
// K7: HMMA MLP. 8 warps tiled 4(m) x 2(n): warp owns 32 rows x 64 cols.
// smem: b1s | b2s | Ah | Al | W1h | W1l | W2h | W2l
// ---------------------------------------------------------------------------
#define SM_AH   1024
#define SM_AL   (SM_AH  + TBYTES)
#define SM_W1H  (SM_AL  + TBYTES)
#define SM_W1L  (SM_W1H + TBYTES)
#define SM_W2H  (SM_W1L + TBYTES)
#define SM_W2L  (SM_W2H + TBYTES)
#define SM_TOT  (SM_W2L + TBYTES)

// acc layout: acc[im*8 + jn*2 + h][4], im in 0..1, jn in 0..3, h = n8 half
__device__ __forceinline__ void do_gemm(const uint32_t aH[2], const uint32_t aL[2],
                                        uint32_t wH, uint32_t wL,
                                        float (*acc)[4]) {
    #pragma unroll
    for (int k = 0; k < 8; k++) {
        uint32_t ah[2][4], al[2][4];
        #pragma unroll
        for (int im = 0; im < 2; im++) {
            ldmx4(aH[im] + k * 32, ah[im]);
            ldmx4(aL[im] + k * 32, al[im]);
        }
        #pragma unroll
        for (int jn = 0; jn < 4; jn++) {
            uint32_t boff = (uint32_t)(jn * 16 * PA * 2 + k * 32);
            uint32_t bh[4], bl[4];
            ldmx4(wH + boff, bh);
            ldmx4(wL + boff, bl);
            #pragma unroll
            for (int im = 0; im < 2; im++) {
                float* c0 = acc[im * 8 + jn * 2];
                float* c1 = acc[im * 8 + jn * 2 + 1];
                mma16816(c0, ah[im], bh[0], bh[1]);
                mma16816(c0, ah[im], bl[0], bl[1]);
                mma16816(c0, al[im], bh[0], bh[1]);
                mma16816(c1, ah[im], bh[2], bh[3]);
                mma16816(c1, ah[im], bl[2], bl[3]);
                mma16816(c1, al[im], bh[2], bh[3]);
            }
        }
    }
}

__global__ void __launch_bounds__(256, 1)
mlp_hmma_kernel(const float* __restrict__ b1,
                const float* __restrict__ b2,
                float* __restrict__ out, int M) {
    extern __shared__ unsigned char sm[];
    const uint32_t sb = smem_u32(sm);
    const int tid  = threadIdx.x;
    const int w    = tid >> 5;
    const int lane = tid & 31;
    const int wm   = w >> 1;          // 0..3
    const int wn   = w & 1;           // 0..1
    const int rowBase = blockIdx.x * TILE_M;

    float* b1s = reinterpret_cast<float*>(sm);
    float* b2s = reinterpret_cast<float*>(sm + 512);
    if (tid < DIM) {
        b1s[tid] = b1[tid];
        b2s[tid] = b2[tid];
    }

    // weight tiles (linear coalesced copy)
    {
        const uint4* s1h = reinterpret_cast<const uint4*>(g_w1h);
        const uint4* s1l = reinterpret_cast<const uint4*>(g_w1l);
        const uint4* s2h = reinterpret_cast<const uint4*>(g_w2h);
        const uint4* s2l = reinterpret_cast<const uint4*>(g_w2l);
        uint4* d1h = reinterpret_cast<uint4*>(sm + SM_W1H);
        uint4* d1l = reinterpret_cast<uint4*>(sm + SM_W1L);
        uint4* d2h = reinterpret_cast<uint4*>(sm + SM_W2H);
        uint4* d2l = reinterpret_cast<uint4*>(sm + SM_W2L);
        for (int i = tid; i < TBYTES / 16; i += 256) {
            d1h[i] = s1h[i]; d1l[i] = s1l[i];
            d2h[i] = s2h[i]; d2l[i] = s2l[i];
        }
    }

    // A tile: load agg rows, split bf16 hi/lo, [m][k] pitch PA
    {
        __nv_bfloat16* Ah = reinterpret_cast<__nv_bfloat16*>(sm + SM_AH);
        __nv_bfloat16* Al = reinterpret_cast<__nv_bfloat16*>(sm + SM_AL);
        const float4* in4 = reinterpret_cast<const float4*>(g_agg);
        #pragma unroll
        for (int i = tid; i < TILE_M * 32; i += 256) {
            int m = i >> 5, c = i & 31;
            int gm = rowBase + m;
            float4 v = make_float4(0.f, 0.f, 0.f, 0.f);
            if (gm < M) v = in4[(size_t)gm * 32 + c];
            float vv[4] = {v.x, v.y, v.z, v.w};
            #pragma unroll
            for (int j = 0; j < 4; j++) {
                __nv_bfloat16 h, l;
                bf16_split(vv[j], h, l);
                Ah[m * PA + c * 4 + j] = h;
                Al[m * PA + c * 4 + j] = l;
            }
        }
    }
    __syncthreads();

    // ldmatrix lane addressing
    // A m16k16: row = row0 + (lane&15), col-half = (lane>>4)*8
    uint32_t aH[2], aL[2];
    #pragma unroll
    for (int im = 0; im < 2; im++) {
        uint32_t off = (uint32_t)(((wm * 32 + im * 16 + (lane & 15)) * PA
                                   + ((lane >> 4) << 3)) * 2);
        aH[im] = sb + SM_AH + off;
        aL[im] = sb + SM_AL + off;
    }
    // B n16k16 from W^T[n][k]: row = (lane&7) + ((lane>>4)<<3), col = ((lane>>3)&1)<<3
    const uint32_t bLaneOff =
        (uint32_t)((((lane & 7) + ((lane >> 4) << 3) + wn * 64) * PA
                    + (((lane >> 3) & 1) << 3)) * 2);

    float acc[16][4];
    #pragma unroll
    for (int i = 0; i < 16; i++)
        #pragma unroll
        for (int j = 0; j < 4; j++) acc[i][j] = 0.f;

    // ---- GEMM1 ----
    do_gemm(aH, aL, sb + SM_W1H + bLaneOff, sb + SM_W1L + bLaneOff, acc);

    // ---- epilogue 1: +b1, relu, split -> H into Ah/Al ----
    {
        __nv_bfloat16* Ah = reinterpret_cast<__nv_bfloat16*>(sm + SM_AH);
        __nv_bfloat16* Al = reinterpret_cast<__nv_bfloat16*>(sm + SM_AL);
        #pragma unroll
        for (int im = 0; im < 2; im++) {
            int r0 = wm * 32 + im * 16 + (lane >> 2);
            int r1 = r0 + 8;
            #pragma unroll
            for (int jn = 0; jn < 4; jn++) {
                #pragma unroll
                for (int h = 0; h < 2; h++) {
                    float* c = acc[im * 8 + jn * 2 + h];
                    int n = wn * 64 + jn * 16 + h * 8 + 2 * (lane & 3);
                    float f00 = c[0] + b1s[n];
                    float f01 = c[1] + b1s[n + 1];
                    float f10 = c[2] + b1s[n];
                    float f11 = c[3] + b1s[n + 1];
                    f00 = f00 > 0.f ? f00 : 0.f;  f01 = f01 > 0.f ? f01 : 0.f;
                    f10 = f10 > 0.f ? f10 : 0.f;  f11 = f11 > 0.f ? f11 : 0.f;
                    __nv_bfloat16 hh, ll;
                    bf16_split(f00, hh, ll); Ah[r0*PA + n]   = hh; Al[r0*PA + n]   = ll;
                    bf16_split(f01, hh, ll); Ah[r0*PA + n+1] = hh; Al[r0*PA + n+1] = ll;
                    bf16_split(f10, hh, ll); Ah[r1*PA + n]   = hh; Al[r1*PA + n]   = ll;
                    bf16_split(f11, hh, ll); Ah[r1*PA + n+1] = hh; Al[r1*PA + n+1] = ll;
                    c[0] = c[1] = c[2] = c[3] = 0.f;
                }
            }
        }
    }
    __syncthreads();   // H cols of a row written by both n-warps

    // ---- GEMM2 ----
    do_gemm(aH, aL, sb + SM_W2H + bLaneOff, sb + SM_W2L + bLaneOff, acc);

    // ---- epilogue 2: +b2, store fp32 ----
    #pragma unroll
    for (int im = 0; im < 2; im++) {
        int gm0 = rowBase + wm * 32 + im * 16 + (lane >> 2);
        int gm1 = gm0 + 8;
        #pragma unroll
        for (int jn = 0; jn < 4; jn++) {
            #pragma unroll
            for (int h = 0; h < 2; h++) {
                float* c = acc[im * 8 + jn * 2 + h];
                int n = wn * 64 + jn * 16 + h * 8 + 2 * (lane & 3);
                if (gm0 < M) {
                    float2 o = make_float2(c[0] + b2s[n], c[1] + b2s[n + 1]);
                    *reinterpret_cast<float2*>(&out[(size_t)gm0 * DIM + n]) = o;
                }
                if (gm1 < M) {
                    float2 o = make_float2(c[2] + b2s[n], c[3] + b2s[n + 1]);
                    *reinterpret_cast<float2*>(&out[(size_t)gm1 * DIM + n]) = o;
                }
            }
        }
    }
}

// ---------------------------------------------------------------------------
// launch
// ---------------------------------------------------------------------------
extern "C" void kernel_launch(void* const* d_in, const int* in_sizes, int n_in,
                              void* d_out, int out_size) {
    const float* x   = (const float*)d_in[0];
    const int*   ei  = (const int*)d_in[1];
    const float* W1  = (const float*)d_in[2];
    const float* b1  = (const float*)d_in[3];
    const float* W2  = (const float*)d_in[4];
    const float* b2  = (const float*)d_in[5];
    float*       out = (float*)d_out;

    const int M = in_sizes[0] / DIM;   // 50000
    const int E = in_sizes[1] / 2;     // 640000
    const int nChunks = (M + 1023) / 1024;

    prep_zero<<<(M + 255) / 256, 256>>>(W1, W2, M);
    hist_kernel<<<(E + 255) / 256, 256>>>(ei, E);
    scan1_kernel<<<nChunks, 1024>>>(M);
    scan2_kernel<<<1, 64>>>(nChunks);
    scan3_kernel<<<(M + 255) / 256, 256>>>(M);
    fill_kernel<<<(E + 255) / 256, 256>>>(ei, E);
    gather_kernel<<<(M + 7) / 8, 256>>>(
        reinterpret_cast<const float4*>(x), M);

    cudaFuncSetAttribute(mlp_hmma_kernel,
                         cudaFuncAttributeMaxDynamicSharedMemorySize, SM_TOT);
    mlp_hmma_kernel<<<(M + TILE_M - 1) / TILE_M, 256, SM_TOT>>>(b1, b2, out, M);
}